// round 6
// baseline (speedup 1.0000x reference)
#include <cuda_runtime.h>
#include <cuda_bf16.h>
#include <stdint.h>
#include <math.h>

#define Zb 2
#define Nn 2048
#define DM 1024
#define Hh 16
#define DKk 64
#define Tt (Zb*Nn)   // 4096

// ---------------- scratch (no allocations allowed) ----------------
__device__ __align__(16) float g_Q[Zb*Hh*Nn*DKk];
__device__ __align__(16) float g_K[Zb*Hh*Nn*DKk];
__device__ __align__(16) float g_V[Zb*Hh*Nn*DKk];
__device__ int g_mask[Tt];
// bf16 hi/lo split operands
__device__ __align__(16) __nv_bfloat16 g_xh[Tt*DM];
__device__ __align__(16) __nv_bfloat16 g_xl[Tt*DM];
__device__ __align__(16) __nv_bfloat16 g_wth[3*Hh*DKk*DM];  // [n=3072][k=1024]
__device__ __align__(16) __nv_bfloat16 g_wtl[3*Hh*DKk*DM];
__device__ __align__(16) __nv_bfloat16 g_woh[DM*DM];        // [n][k]
__device__ __align__(16) __nv_bfloat16 g_wol[DM*DM];
__device__ __align__(16) __nv_bfloat16 g_ctxh[Tt*DM];
__device__ __align__(16) __nv_bfloat16 g_ctxl[Tt*DM];

// ---------------- helpers ----------------
__device__ __forceinline__ uint32_t smem_u32(const void* p) {
    uint32_t a;
    asm("{ .reg .u64 t; cvta.to.shared.u64 t, %1; cvt.u32.u64 %0, t; }"
        : "=r"(a) : "l"(p));
    return a;
}
__device__ __forceinline__ void ldsm4(uint32_t addr, uint32_t* r) {
    asm volatile("ldmatrix.sync.aligned.m8n8.x4.shared.b16 {%0,%1,%2,%3}, [%4];"
                 : "=r"(r[0]), "=r"(r[1]), "=r"(r[2]), "=r"(r[3]) : "r"(addr));
}
__device__ __forceinline__ void mma16816(float* c, const uint32_t* a,
                                         const uint32_t* b) {
    asm volatile(
        "mma.sync.aligned.m16n8k16.row.col.f32.bf16.bf16.f32 "
        "{%0,%1,%2,%3}, {%4,%5,%6,%7}, {%8,%9}, {%0,%1,%2,%3};"
        : "+f"(c[0]), "+f"(c[1]), "+f"(c[2]), "+f"(c[3])
        : "r"(a[0]), "r"(a[1]), "r"(a[2]), "r"(a[3]), "r"(b[0]), "r"(b[1]));
}
__device__ __forceinline__ void cpasync16(uint32_t dst, const void* src) {
    asm volatile("cp.async.cg.shared.global [%0], [%1], 16;"
                 :: "r"(dst), "l"(src) : "memory");
}
#define CP_COMMIT()  asm volatile("cp.async.commit_group;" ::: "memory")
#define CP_WAIT1()   asm volatile("cp.async.wait_group 1;" ::: "memory")
#define CP_WAIT0()   asm volatile("cp.async.wait_group 0;" ::: "memory")

__device__ __forceinline__ uint32_t pack_bf2(float a, float b) {
    __nv_bfloat162 t = __floats2bfloat162_rn(a, b);
    return *(uint32_t*)&t;
}

// ---------------- mask dtype detection + expansion ----------------
__global__ void mask_kernel(const unsigned char* __restrict__ raw) {
    __shared__ int s_gt1, s_off;
    int tid = threadIdx.x;
    if (tid == 0) { s_gt1 = 0; s_off = 0; }
    __syncthreads();
    int gt1 = 0, off = 0;
    for (int i = tid; i < Tt; i += blockDim.x) {
        unsigned char b = raw[i];
        if (b > 1) gt1 = 1;
        if (b && (i & 3)) off = 1;
    }
    if (gt1) atomicOr(&s_gt1, 1);
    if (off) atomicOr(&s_off, 1);
    __syncthreads();
    int mode = s_gt1 ? 2 : (s_off ? 0 : 1);  // 0=bool, 1=int32, 2=float32
    for (int i = tid; i < Tt; i += blockDim.x) {
        int v;
        if (mode == 0)      v = (raw[i] != 0);
        else if (mode == 1) v = (((const int*)raw)[i] != 0);
        else                v = (((const float*)raw)[i] != 0.0f);
        g_mask[i] = v;
    }
}

// ---------------- fp32 -> bf16 hi/lo elementwise split ----------------
__global__ void split_kernel(const float* __restrict__ in,
                             __nv_bfloat16* __restrict__ hi,
                             __nv_bfloat16* __restrict__ lo, int n) {
    int i = blockIdx.x * blockDim.x + threadIdx.x;
    if (i < n) {
        float v = in[i];
        __nv_bfloat16 h = __float2bfloat16_rn(v);
        hi[i] = h;
        lo[i] = __float2bfloat16_rn(v - __bfloat162float(h));
    }
}

// ---------------- QKV weight transpose + split: W[h][d][c] -> wt[n][k] ----------------
__global__ __launch_bounds__(256) void wsplit_kernel(
    const float* __restrict__ qp, const float* __restrict__ kp,
    const float* __restrict__ vp) {
    __shared__ float s[64][68];
    int which = blockIdx.y >> 4, h = blockIdx.y & 15;
    const float* W = (which == 0 ? qp : which == 1 ? kp : vp) + h * DM * DKk;
    int d0 = blockIdx.x * 64;
    int tid = threadIdx.x;
    #pragma unroll
    for (int i = 0; i < 4; i++) {
        int idx = tid + i * 256;
        int r = idx >> 4, c4 = idx & 15;
        float4 v = *(const float4*)&W[(d0 + r) * DKk + c4 * 4];
        s[r][c4 * 4 + 0] = v.x; s[r][c4 * 4 + 1] = v.y;
        s[r][c4 * 4 + 2] = v.z; s[r][c4 * 4 + 3] = v.w;
    }
    __syncthreads();
    #pragma unroll
    for (int i = 0; i < 4; i++) {
        int idx = tid + i * 256;
        int c = idx >> 4, r4 = idx & 15;
        int n = which * 1024 + h * 64 + c;
        size_t base = (size_t)n * DM + d0 + r4 * 4;
        #pragma unroll
        for (int j = 0; j < 4; j++) {
            float v = s[r4 * 4 + j][c];
            __nv_bfloat16 hh = __float2bfloat16_rn(v);
            g_wth[base + j] = hh;
            g_wtl[base + j] = __float2bfloat16_rn(v - __bfloat162float(hh));
        }
    }
}

// ---------------- HMMA split-bf16 GEMM: D[128][128] tiles = A @ B^T ----------------
// A [4096][1024] K-major bf16 hi/lo; B [Ncols][1024] K-major bf16 hi/lo.
// K-chunk 64, double-buffered cp.async, 8 warps (2x4), warp tile 64x32.
// Smem rows: 64 bf16 (128B) + 16B pad = 144B stride -> conflict-free ldmatrix.
#define ROWB 144                        // bytes per smem row
#define TILEB (128 * ROWB)              // 18432 bytes per matrix tile
#define BUFB  (4 * TILEB)               // Ah, Al, Bh, Bl = 73728
#define GEMM_SMEM (2 * BUFB)            // double buffer = 147456

__global__ __launch_bounds__(256) void gemm_bf16x3_kernel(
    const __nv_bfloat16* __restrict__ Ah, const __nv_bfloat16* __restrict__ Al,
    const __nv_bfloat16* __restrict__ Bh, const __nv_bfloat16* __restrict__ Bl,
    const float* __restrict__ qb, const float* __restrict__ kb,
    const float* __restrict__ vb, float* __restrict__ outp, int mode) {
    extern __shared__ __align__(16) char dynsm[];
    __shared__ float s_bias[128];

    int tid = threadIdx.x, wid = tid >> 5, lane = tid & 31;
    int t0 = blockIdx.x * 128, n0 = blockIdx.y * 128;
    uint32_t sbase = smem_u32(dynsm);

    if (tid < 128) {
        if (mode == 0) {
            int n = n0 + tid;
            int which = n >> 10, hd = n & 1023;
            s_bias[tid] = (which == 0 ? qb : which == 1 ? kb : vb)[hd];
        } else {
            s_bias[tid] = 0.0f;
        }
    }

    // per-thread load slots: 4096 x 16B per chunk, 16 per thread
    // idx = tid + i*256; tile = idx>>10, row = (idx>>3)&127, u = idx&7
    // issue loads for chunk c into buffer (c&1)
    auto issue_loads = [&](int c) {
        int k0 = c * 64;
        uint32_t dbase = sbase + (c & 1) * BUFB;
        #pragma unroll
        for (int i = 0; i < 16; i++) {
            int idx = tid + i * 256;
            int tile = idx >> 10, row = (idx >> 3) & 127, u = idx & 7;
            uint32_t dst = dbase + tile * TILEB + row * ROWB + u * 16;
            const __nv_bfloat16* src;
            if (tile == 0)      src = Ah + (size_t)(t0 + row) * DM + k0 + u * 8;
            else if (tile == 1) src = Al + (size_t)(t0 + row) * DM + k0 + u * 8;
            else if (tile == 2) src = Bh + (size_t)(n0 + row) * DM + k0 + u * 8;
            else                src = Bl + (size_t)(n0 + row) * DM + k0 + u * 8;
            cpasync16(dst, src);
        }
        CP_COMMIT();
    };

    float acc[4][4][4];
    #pragma unroll
    for (int i = 0; i < 4; i++)
        #pragma unroll
        for (int j = 0; j < 4; j++)
            #pragma unroll
            for (int q = 0; q < 4; q++) acc[i][j][q] = 0.0f;

    int wm = (wid >> 2) * 64;   // warp row offset (0 or 64)
    int wn = (wid & 3) * 32;    // warp col offset (0..96)
    // ldmatrix lane address components
    int a_r = lane & 15;                       // A: row within m16
    int a_k = (lane >> 4) << 3;                // A: k halfword offset (0 or 8)
    int b_r = ((lane >> 4) << 3) + (lane & 7); // B: row within n16
    int b_k = ((lane >> 3) & 1) << 3;          // B: k halfword offset

    issue_loads(0);

    for (int c = 0; c < 16; c++) {
        if (c + 1 < 16) { issue_loads(c + 1); CP_WAIT1(); }
        else            { CP_WAIT0(); }
        __syncthreads();

        uint32_t sb = sbase + (c & 1) * BUFB;
        uint32_t ahb = sb, alb = sb + TILEB, bhb = sb + 2 * TILEB, blb = sb + 3 * TILEB;

        #pragma unroll
        for (int ks = 0; ks < 4; ks++) {
            int k0 = ks * 16;
            uint32_t ah[4][4], al[4][4], bh[2][4], bl[2][4];
            #pragma unroll
            for (int mt = 0; mt < 4; mt++) {
                uint32_t roff = (wm + mt * 16 + a_r) * ROWB + (k0 + a_k) * 2;
                ldsm4(ahb + roff, ah[mt]);
                ldsm4(alb + roff, al[mt]);
            }
            #pragma unroll
            for (int p = 0; p < 2; p++) {
                uint32_t roff = (wn + p * 16 + b_r) * ROWB + (k0 + b_k) * 2;
                ldsm4(bhb + roff, bh[p]);
                ldsm4(blb + roff, bl[p]);
            }
            #pragma unroll
            for (int mt = 0; mt < 4; mt++)
                #pragma unroll
                for (int nt = 0; nt < 4; nt++) {
                    const uint32_t* bhf = &bh[nt >> 1][(nt & 1) * 2];
                    const uint32_t* blf = &bl[nt >> 1][(nt & 1) * 2];
                    mma16816(acc[mt][nt], ah[mt], bhf);
                    mma16816(acc[mt][nt], ah[mt], blf);
                    mma16816(acc[mt][nt], al[mt], bhf);
                }
        }
        __syncthreads();
    }

    // epilogue: c0,c1 = (r, c),(r, c+1); c2,c3 = (r+8, c),(r+8, c+1)
    int er = lane >> 2, ec = (lane & 3) * 2;
    #pragma unroll
    for (int mt = 0; mt < 4; mt++)
        #pragma unroll
        for (int nt = 0; nt < 4; nt++) {
            int gcol = n0 + wn + nt * 8 + ec;
            float b0 = s_bias[gcol - n0], b1 = s_bias[gcol - n0 + 1];
            #pragma unroll
            for (int half = 0; half < 2; half++) {
                int grow = t0 + wm + mt * 16 + er + half * 8;
                float2 v = make_float2(acc[mt][nt][half * 2 + 0] + b0,
                                       acc[mt][nt][half * 2 + 1] + b1);
                if (mode == 0) {
                    int which = gcol >> 10, hh = (gcol >> 6) & 15, dk = gcol & 63;
                    int z = grow >> 11, nnn = grow & (Nn - 1);
                    float* dst = which == 0 ? g_Q : which == 1 ? g_K : g_V;
                    *(float2*)&dst[((size_t)(z * Hh + hh) * Nn + nnn) * DKk + dk] = v;
                } else {
                    *(float2*)&outp[(size_t)grow * DM + gcol] = v;
                }
            }
        }
}

// ---------------- flash attention (SIMT fp32) ----------------
#define SApad 132
#define ATTN_SMEM ((64 * SApad * 2 + 64 * 68 * 2) * 4)

__global__ __launch_bounds__(256) void attn_kernel() {
    extern __shared__ __align__(16) float sm[];
    float* Qs = sm;                          // [d][q]   64 x 132
    float* Kt = Qs + 64 * SApad;             // [d][key] 64 x 68
    float* Vs = Kt + 64 * 68;                // [key][d] 64 x 68
    float* Pt = Vs + 64 * 68;                // [key][q] 64 x 132

    int tid = threadIdx.x, tx = tid & 15, ty = tid >> 4;
    int q0 = blockIdx.x * 128;
    int h = blockIdx.y, z = blockIdx.z;
    const float* Qg = g_Q + (size_t)((z * Hh + h) * Nn) * DKk;
    const float* Kg = g_K + (size_t)((z * Hh + h) * Nn) * DKk;
    const float* Vg = g_V + (size_t)((z * Hh + h) * Nn) * DKk;

    #pragma unroll
    for (int it = 0; it < 8; it++) {
        int idx = tid + it * 256;
        int q = idx >> 4, d4 = idx & 15;
        float4 v4 = *(const float4*)&Qg[(q0 + q) * DKk + d4 * 4];
        Qs[(d4 * 4 + 0) * SApad + q] = v4.x;
        Qs[(d4 * 4 + 1) * SApad + q] = v4.y;
        Qs[(d4 * 4 + 2) * SApad + q] = v4.z;
        Qs[(d4 * 4 + 3) * SApad + q] = v4.w;
    }

    float m_i[8], l_i[8], acc[8][4];
    #pragma unroll
    for (int i = 0; i < 8; i++) {
        m_i[i] = -1e30f; l_i[i] = 0.0f;
        #pragma unroll
        for (int j = 0; j < 4; j++) acc[i][j] = 0.0f;
    }
    const float scale = 0.125f;

    for (int k0 = 0; k0 < Nn; k0 += 64) {
        __syncthreads();
        #pragma unroll
        for (int it = 0; it < 4; it++) {
            int idx = tid + it * 256;
            int key = idx >> 4, d4 = idx & 15;
            float4 kv = *(const float4*)&Kg[(k0 + key) * DKk + d4 * 4];
            Kt[(d4 * 4 + 0) * 68 + key] = kv.x;
            Kt[(d4 * 4 + 1) * 68 + key] = kv.y;
            Kt[(d4 * 4 + 2) * 68 + key] = kv.z;
            Kt[(d4 * 4 + 3) * 68 + key] = kv.w;
            *(float4*)&Vs[key * 68 + d4 * 4] =
                *(const float4*)&Vg[(k0 + key) * DKk + d4 * 4];
        }
        __syncthreads();

        float s[8][4] = {};
        #pragma unroll 16
        for (int kk = 0; kk < 64; kk++) {
            float4 b4 = *(float4*)&Kt[kk * 68 + tx * 4];
            float bb[4] = {b4.x, b4.y, b4.z, b4.w};
            float4 a0 = *(float4*)&Qs[kk * SApad + ty * 4];
            float4 a1 = *(float4*)&Qs[kk * SApad + 64 + ty * 4];
            float aa[8] = {a0.x, a0.y, a0.z, a0.w, a1.x, a1.y, a1.z, a1.w};
            #pragma unroll
            for (int i = 0; i < 8; i++)
                #pragma unroll
                for (int j = 0; j < 4; j++) s[i][j] += aa[i] * bb[j];
        }

        int kvalid[4];
        #pragma unroll
        for (int j = 0; j < 4; j++) kvalid[j] = g_mask[z * Nn + k0 + tx * 4 + j];
        #pragma unroll
        for (int i = 0; i < 8; i++)
            #pragma unroll
            for (int j = 0; j < 4; j++)
                s[i][j] = kvalid[j] ? s[i][j] * scale : -1e9f;

        #pragma unroll
        for (int i = 0; i < 8; i++) {
            float tm = fmaxf(fmaxf(s[i][0], s[i][1]), fmaxf(s[i][2], s[i][3]));
            #pragma unroll
            for (int off = 8; off; off >>= 1)
                tm = fmaxf(tm, __shfl_xor_sync(0xffffffffu, tm, off));
            float mnew = fmaxf(m_i[i], tm);
            float fac = __expf(m_i[i] - mnew);
            float ps = 0.0f;
            #pragma unroll
            for (int j = 0; j < 4; j++) {
                s[i][j] = __expf(s[i][j] - mnew);
                ps += s[i][j];
            }
            #pragma unroll
            for (int off = 8; off; off >>= 1)
                ps += __shfl_xor_sync(0xffffffffu, ps, off);
            l_i[i] = l_i[i] * fac + ps;
            m_i[i] = mnew;
            #pragma unroll
            for (int j = 0; j < 4; j++) acc[i][j] *= fac;
        }
        #pragma unroll
        for (int j = 0; j < 4; j++) {
            int key = tx * 4 + j;
            *(float4*)&Pt[key * SApad + ty * 4] =
                make_float4(s[0][j], s[1][j], s[2][j], s[3][j]);
            *(float4*)&Pt[key * SApad + 64 + ty * 4] =
                make_float4(s[4][j], s[5][j], s[6][j], s[7][j]);
        }
        __syncthreads();

        #pragma unroll 16
        for (int kk = 0; kk < 64; kk++) {
            float4 b4 = *(float4*)&Vs[kk * 68 + tx * 4];
            float bb[4] = {b4.x, b4.y, b4.z, b4.w};
            float4 a0 = *(float4*)&Pt[kk * SApad + ty * 4];
            float4 a1 = *(float4*)&Pt[kk * SApad + 64 + ty * 4];
            float aa[8] = {a0.x, a0.y, a0.z, a0.w, a1.x, a1.y, a1.z, a1.w};
            #pragma unroll
            for (int i = 0; i < 8; i++)
                #pragma unroll
                for (int j = 0; j < 4; j++) acc[i][j] += aa[i] * bb[j];
        }
    }

    // epilogue: normalize, zero invalid queries, write ctx as bf16 hi/lo
    #pragma unroll
    for (int i = 0; i < 8; i++) {
        int r = (i < 4) ? (ty * 4 + i) : (64 + ty * 4 + (i - 4));
        int q = q0 + r;
        float inv = g_mask[z * Nn + q] ? (1.0f / l_i[i]) : 0.0f;
        float v0 = acc[i][0] * inv, v1 = acc[i][1] * inv;
        float v2 = acc[i][2] * inv, v3 = acc[i][3] * inv;
        size_t base = (size_t)(z * Nn + q) * DM + h * DKk + tx * 4;
        __nv_bfloat16 h0 = __float2bfloat16_rn(v0), h1 = __float2bfloat16_rn(v1);
        __nv_bfloat16 h2 = __float2bfloat16_rn(v2), h3 = __float2bfloat16_rn(v3);
        uint2 hv, lv;
        hv.x = pack_bf2(v0, v1); hv.y = pack_bf2(v2, v3);
        lv.x = pack_bf2(v0 - __bfloat162float(h0), v1 - __bfloat162float(h1));
        lv.y = pack_bf2(v2 - __bfloat162float(h2), v3 - __bfloat162float(h3));
        *(uint2*)&g_ctxh[base] = hv;
        *(uint2*)&g_ctxl[base] = lv;
    }
}

// ---------------- launch ----------------
extern "C" void kernel_launch(void* const* d_in, const int* in_sizes, int n_in,
                              void* d_out, int out_size) {
    const float* x  = (const float*)d_in[0];
    const unsigned char* mraw = (const unsigned char*)d_in[1];
    const float* qp = (const float*)d_in[2];
    const float* kp = (const float*)d_in[3];
    const float* vp = (const float*)d_in[4];
    const float* qb = (const float*)d_in[5];
    const float* kb = (const float*)d_in[6];
    const float* vb = (const float*)d_in[7];
    const float* ow = (const float*)d_in[8];
    float* out = (float*)d_out;

    __nv_bfloat16 *xh_p, *xl_p, *wth_p, *wtl_p, *woh_p, *wol_p, *ctxh_p, *ctxl_p;
    cudaGetSymbolAddress((void**)&xh_p,  g_xh);
    cudaGetSymbolAddress((void**)&xl_p,  g_xl);
    cudaGetSymbolAddress((void**)&wth_p, g_wth);
    cudaGetSymbolAddress((void**)&wtl_p, g_wtl);
    cudaGetSymbolAddress((void**)&woh_p, g_woh);
    cudaGetSymbolAddress((void**)&wol_p, g_wol);
    cudaGetSymbolAddress((void**)&ctxh_p, g_ctxh);
    cudaGetSymbolAddress((void**)&ctxl_p, g_ctxl);
    cudaFuncSetAttribute(attn_kernel,
                         cudaFuncAttributeMaxDynamicSharedMemorySize, ATTN_SMEM);
    cudaFuncSetAttribute(gemm_bf16x3_kernel,
                         cudaFuncAttributeMaxDynamicSharedMemorySize, GEMM_SMEM);

    mask_kernel<<<1, 256>>>(mraw);
    split_kernel<<<(Tt * DM) / 256, 256>>>(x, xh_p, xl_p, Tt * DM);
    wsplit_kernel<<<dim3(DM / 64, 3 * Hh), 256>>>(qp, kp, vp);
    split_kernel<<<(DM * DM) / 256, 256>>>(ow, woh_p, wol_p, DM * DM);

    // QKV: A = x (hi/lo), B = wt [3072][1024]
    gemm_bf16x3_kernel<<<dim3(Tt / 128, 3 * Hh * DKk / 128), 256, GEMM_SMEM>>>(
        xh_p, xl_p, wth_p, wtl_p, qb, kb, vb, nullptr, 0);

    attn_kernel<<<dim3(Nn / 128, Hh, Zb), 256, ATTN_SMEM>>>();

    // out-proj: A = ctx (hi/lo), B = Wo [1024][1024]
    gemm_bf16x3_kernel<<<dim3(Tt / 128, DM / 128), 256, GEMM_SMEM>>>(
        ctxh_p, ctxl_p, woh_p, wol_p, nullptr, nullptr, nullptr, out, 1);
}

// round 7
// speedup vs baseline: 1.6161x; 1.6161x over previous
#include <cuda_runtime.h>
#include <cuda_bf16.h>
#include <stdint.h>
#include <math.h>

#define Zb 2
#define Nn 2048
#define DM 1024
#define Hh 16
#define DKk 64
#define Tt (Zb*Nn)   // 4096

// ---------------- scratch (no allocations allowed) ----------------
__device__ __align__(16) float g_Q[Zb*Hh*Nn*DKk];
__device__ __align__(16) float g_K[Zb*Hh*Nn*DKk];
__device__ __align__(16) float g_V[Zb*Hh*Nn*DKk];
__device__ int g_mask[Tt];
// bf16 hi/lo split operands
__device__ __align__(16) __nv_bfloat16 g_xh[Tt*DM];
__device__ __align__(16) __nv_bfloat16 g_xl[Tt*DM];
__device__ __align__(16) __nv_bfloat16 g_wth[3*Hh*DKk*DM];  // [n=3072][k=1024]
__device__ __align__(16) __nv_bfloat16 g_wtl[3*Hh*DKk*DM];
__device__ __align__(16) __nv_bfloat16 g_woh[DM*DM];        // [n][k]
__device__ __align__(16) __nv_bfloat16 g_wol[DM*DM];
__device__ __align__(16) __nv_bfloat16 g_ctxh[Tt*DM];
__device__ __align__(16) __nv_bfloat16 g_ctxl[Tt*DM];

// ---------------- helpers ----------------
__device__ __forceinline__ uint32_t smem_u32(const void* p) {
    uint32_t a;
    asm("{ .reg .u64 t; cvta.to.shared.u64 t, %1; cvt.u32.u64 %0, t; }"
        : "=r"(a) : "l"(p));
    return a;
}
__device__ __forceinline__ void ldsm4(uint32_t addr, uint32_t* r) {
    asm volatile("ldmatrix.sync.aligned.m8n8.x4.shared.b16 {%0,%1,%2,%3}, [%4];"
                 : "=r"(r[0]), "=r"(r[1]), "=r"(r[2]), "=r"(r[3]) : "r"(addr));
}
__device__ __forceinline__ void mma16816(float* c, const uint32_t* a,
                                         const uint32_t* b) {
    asm volatile(
        "mma.sync.aligned.m16n8k16.row.col.f32.bf16.bf16.f32 "
        "{%0,%1,%2,%3}, {%4,%5,%6,%7}, {%8,%9}, {%0,%1,%2,%3};"
        : "+f"(c[0]), "+f"(c[1]), "+f"(c[2]), "+f"(c[3])
        : "r"(a[0]), "r"(a[1]), "r"(a[2]), "r"(a[3]), "r"(b[0]), "r"(b[1]));
}
__device__ __forceinline__ void cpasync16(uint32_t dst, const void* src) {
    asm volatile("cp.async.cg.shared.global [%0], [%1], 16;"
                 :: "r"(dst), "l"(src) : "memory");
}
#define CP_COMMIT()  asm volatile("cp.async.commit_group;" ::: "memory")
#define CP_WAIT1()   asm volatile("cp.async.wait_group 1;" ::: "memory")
#define CP_WAIT0()   asm volatile("cp.async.wait_group 0;" ::: "memory")

__device__ __forceinline__ uint32_t pack_bf2(float a, float b) {
    __nv_bfloat162 t = __floats2bfloat162_rn(a, b);
    return *(uint32_t*)&t;
}

// ---------------- mask dtype detection + expansion ----------------
__global__ void mask_kernel(const unsigned char* __restrict__ raw) {
    __shared__ int s_gt1, s_off;
    int tid = threadIdx.x;
    if (tid == 0) { s_gt1 = 0; s_off = 0; }
    __syncthreads();
    int gt1 = 0, off = 0;
    for (int i = tid; i < Tt; i += blockDim.x) {
        unsigned char b = raw[i];
        if (b > 1) gt1 = 1;
        if (b && (i & 3)) off = 1;
    }
    if (gt1) atomicOr(&s_gt1, 1);
    if (off) atomicOr(&s_off, 1);
    __syncthreads();
    int mode = s_gt1 ? 2 : (s_off ? 0 : 1);  // 0=bool, 1=int32, 2=float32
    for (int i = tid; i < Tt; i += blockDim.x) {
        int v;
        if (mode == 0)      v = (raw[i] != 0);
        else if (mode == 1) v = (((const int*)raw)[i] != 0);
        else                v = (((const float*)raw)[i] != 0.0f);
        g_mask[i] = v;
    }
}

// ---------------- fp32 -> bf16 hi/lo elementwise split ----------------
__global__ void split_kernel(const float* __restrict__ in,
                             __nv_bfloat16* __restrict__ hi,
                             __nv_bfloat16* __restrict__ lo, int n) {
    int i = blockIdx.x * blockDim.x + threadIdx.x;
    if (i < n) {
        float v = in[i];
        __nv_bfloat16 h = __float2bfloat16_rn(v);
        hi[i] = h;
        lo[i] = __float2bfloat16_rn(v - __bfloat162float(h));
    }
}

// ---------------- QKV weight transpose + split: W[h][d][c] -> wt[n][k] ----------------
__global__ __launch_bounds__(256) void wsplit_kernel(
    const float* __restrict__ qp, const float* __restrict__ kp,
    const float* __restrict__ vp) {
    __shared__ float s[64][68];
    int which = blockIdx.y >> 4, h = blockIdx.y & 15;
    const float* W = (which == 0 ? qp : which == 1 ? kp : vp) + h * DM * DKk;
    int d0 = blockIdx.x * 64;
    int tid = threadIdx.x;
    #pragma unroll
    for (int i = 0; i < 4; i++) {
        int idx = tid + i * 256;
        int r = idx >> 4, c4 = idx & 15;
        float4 v = *(const float4*)&W[(d0 + r) * DKk + c4 * 4];
        s[r][c4 * 4 + 0] = v.x; s[r][c4 * 4 + 1] = v.y;
        s[r][c4 * 4 + 2] = v.z; s[r][c4 * 4 + 3] = v.w;
    }
    __syncthreads();
    #pragma unroll
    for (int i = 0; i < 4; i++) {
        int idx = tid + i * 256;
        int c = idx >> 4, r4 = idx & 15;
        int n = which * 1024 + h * 64 + c;
        size_t base = (size_t)n * DM + d0 + r4 * 4;
        #pragma unroll
        for (int j = 0; j < 4; j++) {
            float v = s[r4 * 4 + j][c];
            __nv_bfloat16 hh = __float2bfloat16_rn(v);
            g_wth[base + j] = hh;
            g_wtl[base + j] = __float2bfloat16_rn(v - __bfloat162float(hh));
        }
    }
}

// ---------------- HMMA split-bf16 GEMM: D[128][128] tiles = A @ B^T ----------------
// K-chunk 32, double-buffered cp.async, 8 warps (2x4), warp tile 64x32.
// Smem rows: 32 bf16 (64B) + 16B pad = 80B stride -> 5r mod 8 covers all
// 16B-columns -> conflict-free ldmatrix. 2 CTAs/SM (80KB smem, <=128 regs).
#define KCH 32
#define ROWB 80                         // bytes per smem row
#define TILEB (128 * ROWB)              // 10240 bytes per matrix tile
#define BUFB  (4 * TILEB)               // Ah, Al, Bh, Bl = 40960
#define GEMM_SMEM (2 * BUFB)            // double buffer = 81920
#define NCHUNK (DM / KCH)               // 32

__global__ __launch_bounds__(256, 2) void gemm_bf16x3_kernel(
    const __nv_bfloat16* __restrict__ Ah, const __nv_bfloat16* __restrict__ Al,
    const __nv_bfloat16* __restrict__ Bh, const __nv_bfloat16* __restrict__ Bl,
    const float* __restrict__ qb, const float* __restrict__ kb,
    const float* __restrict__ vb, float* __restrict__ outp, int mode) {
    extern __shared__ __align__(16) char dynsm[];
    __shared__ float s_bias[128];

    int tid = threadIdx.x, wid = tid >> 5, lane = tid & 31;
    int t0 = blockIdx.x * 128, n0 = blockIdx.y * 128;
    uint32_t sbase = smem_u32(dynsm);

    if (tid < 128) {
        if (mode == 0) {
            int n = n0 + tid;
            int which = n >> 10, hd = n & 1023;
            s_bias[tid] = (which == 0 ? qb : which == 1 ? kb : vb)[hd];
        } else {
            s_bias[tid] = 0.0f;
        }
    }

    // loads per chunk: 4 tiles x 128 rows x 64B = 2048 x 16B; 8 per thread.
    // slot s in [0,8): tile = s>>1 (compile-time), row = (idx>>2)&127, u = idx&3
    const __nv_bfloat16* bases[4] = {Ah, Al, Bh, Bl};
    auto issue_loads = [&](int c) {
        int k0 = c * KCH;
        uint32_t dbase = sbase + (c & 1) * BUFB;
        #pragma unroll
        for (int s = 0; s < 8; s++) {
            const int tile = s >> 1;
            int idx = tid + s * 256;
            int row = (idx >> 2) & 127, u = idx & 3;
            uint32_t dst = dbase + tile * TILEB + row * ROWB + u * 16;
            int grow = (tile < 2) ? (t0 + row) : (n0 + row);
            cpasync16(dst, bases[tile] + (size_t)grow * DM + k0 + u * 8);
        }
        CP_COMMIT();
    };

    float acc[4][4][4];
    #pragma unroll
    for (int i = 0; i < 4; i++)
        #pragma unroll
        for (int j = 0; j < 4; j++)
            #pragma unroll
            for (int q = 0; q < 4; q++) acc[i][j][q] = 0.0f;

    int wm = (wid >> 2) * 64;   // warp row offset (0 or 64)
    int wn = (wid & 3) * 32;    // warp col offset (0..96)
    // ldmatrix lane address components
    int a_r = lane & 15;                       // A: row within m16
    int a_k = (lane >> 4) << 3;                // A: k halfword offset (0 or 8)
    int b_r = ((lane >> 4) << 3) + (lane & 7); // B: row within n16
    int b_k = ((lane >> 3) & 1) << 3;          // B: k halfword offset

    issue_loads(0);

    for (int c = 0; c < NCHUNK; c++) {
        if (c + 1 < NCHUNK) { issue_loads(c + 1); CP_WAIT1(); }
        else                { CP_WAIT0(); }
        __syncthreads();

        uint32_t sb = sbase + (c & 1) * BUFB;
        uint32_t ahb = sb, alb = sb + TILEB, bhb = sb + 2 * TILEB, blb = sb + 3 * TILEB;

        #pragma unroll
        for (int ks = 0; ks < 2; ks++) {
            int k0 = ks * 16;
            uint32_t bh[2][4], bl[2][4];
            #pragma unroll
            for (int p = 0; p < 2; p++) {
                uint32_t roff = (wn + p * 16 + b_r) * ROWB + (k0 + b_k) * 2;
                ldsm4(bhb + roff, bh[p]);
                ldsm4(blb + roff, bl[p]);
            }
            #pragma unroll
            for (int mt = 0; mt < 4; mt++) {
                uint32_t ah[4], al[4];
                uint32_t roff = (wm + mt * 16 + a_r) * ROWB + (k0 + a_k) * 2;
                ldsm4(ahb + roff, ah);
                ldsm4(alb + roff, al);
                #pragma unroll
                for (int nt = 0; nt < 4; nt++) {
                    const uint32_t* bhf = &bh[nt >> 1][(nt & 1) * 2];
                    const uint32_t* blf = &bl[nt >> 1][(nt & 1) * 2];
                    mma16816(acc[mt][nt], ah, bhf);
                    mma16816(acc[mt][nt], ah, blf);
                    mma16816(acc[mt][nt], al, bhf);
                }
            }
        }
        __syncthreads();
    }

    // epilogue: c0,c1 = (r, c),(r, c+1); c2,c3 = (r+8, c),(r+8, c+1)
    int er = lane >> 2, ec = (lane & 3) * 2;
    #pragma unroll
    for (int mt = 0; mt < 4; mt++)
        #pragma unroll
        for (int nt = 0; nt < 4; nt++) {
            int gcol = n0 + wn + nt * 8 + ec;
            float b0 = s_bias[gcol - n0], b1 = s_bias[gcol - n0 + 1];
            #pragma unroll
            for (int half = 0; half < 2; half++) {
                int grow = t0 + wm + mt * 16 + er + half * 8;
                float2 v = make_float2(acc[mt][nt][half * 2 + 0] + b0,
                                       acc[mt][nt][half * 2 + 1] + b1);
                if (mode == 0) {
                    int which = gcol >> 10, hh = (gcol >> 6) & 15, dk = gcol & 63;
                    int z = grow >> 11, nnn = grow & (Nn - 1);
                    float* dst = which == 0 ? g_Q : which == 1 ? g_K : g_V;
                    *(float2*)&dst[((size_t)(z * Hh + hh) * Nn + nnn) * DKk + dk] = v;
                } else {
                    *(float2*)&outp[(size_t)grow * DM + gcol] = v;
                }
            }
        }
}

// ---------------- flash attention (SIMT fp32) ----------------
#define SApad 132
#define ATTN_SMEM ((64 * SApad * 2 + 64 * 68 * 2) * 4)

__global__ __launch_bounds__(256) void attn_kernel() {
    extern __shared__ __align__(16) float sm[];
    float* Qs = sm;                          // [d][q]   64 x 132
    float* Kt = Qs + 64 * SApad;             // [d][key] 64 x 68
    float* Vs = Kt + 64 * 68;                // [key][d] 64 x 68
    float* Pt = Vs + 64 * 68;                // [key][q] 64 x 132

    int tid = threadIdx.x, tx = tid & 15, ty = tid >> 4;
    int q0 = blockIdx.x * 128;
    int h = blockIdx.y, z = blockIdx.z;
    const float* Qg = g_Q + (size_t)((z * Hh + h) * Nn) * DKk;
    const float* Kg = g_K + (size_t)((z * Hh + h) * Nn) * DKk;
    const float* Vg = g_V + (size_t)((z * Hh + h) * Nn) * DKk;

    #pragma unroll
    for (int it = 0; it < 8; it++) {
        int idx = tid + it * 256;
        int q = idx >> 4, d4 = idx & 15;
        float4 v4 = *(const float4*)&Qg[(q0 + q) * DKk + d4 * 4];
        Qs[(d4 * 4 + 0) * SApad + q] = v4.x;
        Qs[(d4 * 4 + 1) * SApad + q] = v4.y;
        Qs[(d4 * 4 + 2) * SApad + q] = v4.z;
        Qs[(d4 * 4 + 3) * SApad + q] = v4.w;
    }

    float m_i[8], l_i[8], acc[8][4];
    #pragma unroll
    for (int i = 0; i < 8; i++) {
        m_i[i] = -1e30f; l_i[i] = 0.0f;
        #pragma unroll
        for (int j = 0; j < 4; j++) acc[i][j] = 0.0f;
    }
    const float scale = 0.125f;

    for (int k0 = 0; k0 < Nn; k0 += 64) {
        __syncthreads();
        #pragma unroll
        for (int it = 0; it < 4; it++) {
            int idx = tid + it * 256;
            int key = idx >> 4, d4 = idx & 15;
            float4 kv = *(const float4*)&Kg[(k0 + key) * DKk + d4 * 4];
            Kt[(d4 * 4 + 0) * 68 + key] = kv.x;
            Kt[(d4 * 4 + 1) * 68 + key] = kv.y;
            Kt[(d4 * 4 + 2) * 68 + key] = kv.z;
            Kt[(d4 * 4 + 3) * 68 + key] = kv.w;
            *(float4*)&Vs[key * 68 + d4 * 4] =
                *(const float4*)&Vg[(k0 + key) * DKk + d4 * 4];
        }
        __syncthreads();

        float s[8][4] = {};
        #pragma unroll 16
        for (int kk = 0; kk < 64; kk++) {
            float4 b4 = *(float4*)&Kt[kk * 68 + tx * 4];
            float bb[4] = {b4.x, b4.y, b4.z, b4.w};
            float4 a0 = *(float4*)&Qs[kk * SApad + ty * 4];
            float4 a1 = *(float4*)&Qs[kk * SApad + 64 + ty * 4];
            float aa[8] = {a0.x, a0.y, a0.z, a0.w, a1.x, a1.y, a1.z, a1.w};
            #pragma unroll
            for (int i = 0; i < 8; i++)
                #pragma unroll
                for (int j = 0; j < 4; j++) s[i][j] += aa[i] * bb[j];
        }

        int kvalid[4];
        #pragma unroll
        for (int j = 0; j < 4; j++) kvalid[j] = g_mask[z * Nn + k0 + tx * 4 + j];
        #pragma unroll
        for (int i = 0; i < 8; i++)
            #pragma unroll
            for (int j = 0; j < 4; j++)
                s[i][j] = kvalid[j] ? s[i][j] * scale : -1e9f;

        #pragma unroll
        for (int i = 0; i < 8; i++) {
            float tm = fmaxf(fmaxf(s[i][0], s[i][1]), fmaxf(s[i][2], s[i][3]));
            #pragma unroll
            for (int off = 8; off; off >>= 1)
                tm = fmaxf(tm, __shfl_xor_sync(0xffffffffu, tm, off));
            float mnew = fmaxf(m_i[i], tm);
            float fac = __expf(m_i[i] - mnew);
            float ps = 0.0f;
            #pragma unroll
            for (int j = 0; j < 4; j++) {
                s[i][j] = __expf(s[i][j] - mnew);
                ps += s[i][j];
            }
            #pragma unroll
            for (int off = 8; off; off >>= 1)
                ps += __shfl_xor_sync(0xffffffffu, ps, off);
            l_i[i] = l_i[i] * fac + ps;
            m_i[i] = mnew;
            #pragma unroll
            for (int j = 0; j < 4; j++) acc[i][j] *= fac;
        }
        #pragma unroll
        for (int j = 0; j < 4; j++) {
            int key = tx * 4 + j;
            *(float4*)&Pt[key * SApad + ty * 4] =
                make_float4(s[0][j], s[1][j], s[2][j], s[3][j]);
            *(float4*)&Pt[key * SApad + 64 + ty * 4] =
                make_float4(s[4][j], s[5][j], s[6][j], s[7][j]);
        }
        __syncthreads();

        #pragma unroll 16
        for (int kk = 0; kk < 64; kk++) {
            float4 b4 = *(float4*)&Vs[kk * 68 + tx * 4];
            float bb[4] = {b4.x, b4.y, b4.z, b4.w};
            float4 a0 = *(float4*)&Pt[kk * SApad + ty * 4];
            float4 a1 = *(float4*)&Pt[kk * SApad + 64 + ty * 4];
            float aa[8] = {a0.x, a0.y, a0.z, a0.w, a1.x, a1.y, a1.z, a1.w};
            #pragma unroll
            for (int i = 0; i < 8; i++)
                #pragma unroll
                for (int j = 0; j < 4; j++) acc[i][j] += aa[i] * bb[j];
        }
    }

    // epilogue: normalize, zero invalid queries, write ctx as bf16 hi/lo
    #pragma unroll
    for (int i = 0; i < 8; i++) {
        int r = (i < 4) ? (ty * 4 + i) : (64 + ty * 4 + (i - 4));
        int q = q0 + r;
        float inv = g_mask[z * Nn + q] ? (1.0f / l_i[i]) : 0.0f;
        float v0 = acc[i][0] * inv, v1 = acc[i][1] * inv;
        float v2 = acc[i][2] * inv, v3 = acc[i][3] * inv;
        size_t base = (size_t)(z * Nn + q) * DM + h * DKk + tx * 4;
        __nv_bfloat16 h0 = __float2bfloat16_rn(v0), h1 = __float2bfloat16_rn(v1);
        __nv_bfloat16 h2 = __float2bfloat16_rn(v2), h3 = __float2bfloat16_rn(v3);
        uint2 hv, lv;
        hv.x = pack_bf2(v0, v1); hv.y = pack_bf2(v2, v3);
        lv.x = pack_bf2(v0 - __bfloat162float(h0), v1 - __bfloat162float(h1));
        lv.y = pack_bf2(v2 - __bfloat162float(h2), v3 - __bfloat162float(h3));
        *(uint2*)&g_ctxh[base] = hv;
        *(uint2*)&g_ctxl[base] = lv;
    }
}

// ---------------- launch ----------------
extern "C" void kernel_launch(void* const* d_in, const int* in_sizes, int n_in,
                              void* d_out, int out_size) {
    const float* x  = (const float*)d_in[0];
    const unsigned char* mraw = (const unsigned char*)d_in[1];
    const float* qp = (const float*)d_in[2];
    const float* kp = (const float*)d_in[3];
    const float* vp = (const float*)d_in[4];
    const float* qb = (const float*)d_in[5];
    const float* kb = (const float*)d_in[6];
    const float* vb = (const float*)d_in[7];
    const float* ow = (const float*)d_in[8];
    float* out = (float*)d_out;

    __nv_bfloat16 *xh_p, *xl_p, *wth_p, *wtl_p, *woh_p, *wol_p, *ctxh_p, *ctxl_p;
    cudaGetSymbolAddress((void**)&xh_p,  g_xh);
    cudaGetSymbolAddress((void**)&xl_p,  g_xl);
    cudaGetSymbolAddress((void**)&wth_p, g_wth);
    cudaGetSymbolAddress((void**)&wtl_p, g_wtl);
    cudaGetSymbolAddress((void**)&woh_p, g_woh);
    cudaGetSymbolAddress((void**)&wol_p, g_wol);
    cudaGetSymbolAddress((void**)&ctxh_p, g_ctxh);
    cudaGetSymbolAddress((void**)&ctxl_p, g_ctxl);
    cudaFuncSetAttribute(attn_kernel,
                         cudaFuncAttributeMaxDynamicSharedMemorySize, ATTN_SMEM);
    cudaFuncSetAttribute(gemm_bf16x3_kernel,
                         cudaFuncAttributeMaxDynamicSharedMemorySize, GEMM_SMEM);

    mask_kernel<<<1, 256>>>(mraw);
    split_kernel<<<(Tt * DM) / 256, 256>>>(x, xh_p, xl_p, Tt * DM);
    wsplit_kernel<<<dim3(DM / 64, 3 * Hh), 256>>>(qp, kp, vp);
    split_kernel<<<(DM * DM) / 256, 256>>>(ow, woh_p, wol_p, DM * DM);

    // QKV: A = x (hi/lo), B = wt [3072][1024]
    gemm_bf16x3_kernel<<<dim3(Tt / 128, 3 * Hh * DKk / 128), 256, GEMM_SMEM>>>(
        xh_p, xl_p, wth_p, wtl_p, qb, kb, vb, nullptr, 0);

    attn_kernel<<<dim3(Nn / 128, Hh, Zb), 256, ATTN_SMEM>>>();

    // out-proj: A = ctx (hi/lo), B = Wo [1024][1024]
    gemm_bf16x3_kernel<<<dim3(Tt / 128, DM / 128), 256, GEMM_SMEM>>>(
        ctxh_p, ctxl_p, woh_p, wol_p, nullptr, nullptr, nullptr, out, 1);
}

// round 11
// speedup vs baseline: 1.9601x; 1.2128x over previous
#include <cuda_runtime.h>
#include <cuda_bf16.h>
#include <stdint.h>
#include <math.h>

#define Zb 2
#define Nn 2048
#define DM 1024
#define Hh 16
#define DKk 64
#define Tt (Zb*Nn)   // 4096

// ---------------- scratch (no allocations allowed) ----------------
__device__ int g_mask[Tt];
// bf16 hi/lo split operands
__device__ __align__(16) __nv_bfloat16 g_xh[Tt*DM];
__device__ __align__(16) __nv_bfloat16 g_xl[Tt*DM];
__device__ __align__(16) __nv_bfloat16 g_wth[3*Hh*DKk*DM];  // [n=3072][k=1024]
__device__ __align__(16) __nv_bfloat16 g_wtl[3*Hh*DKk*DM];
__device__ __align__(16) __nv_bfloat16 g_woh[DM*DM];        // [n][k]
__device__ __align__(16) __nv_bfloat16 g_wol[DM*DM];
__device__ __align__(16) __nv_bfloat16 g_ctxh[Tt*DM];
__device__ __align__(16) __nv_bfloat16 g_ctxl[Tt*DM];
// attention operands (Q pre-scaled by 0.125)
__device__ __align__(16) __nv_bfloat16 g_Qh[Zb*Hh*Nn*DKk];  // [zh][q][d]
__device__ __align__(16) __nv_bfloat16 g_Ql[Zb*Hh*Nn*DKk];
__device__ __align__(16) __nv_bfloat16 g_Kh[Zb*Hh*Nn*DKk];  // [zh][key][d]
__device__ __align__(16) __nv_bfloat16 g_Kl[Zb*Hh*Nn*DKk];
__device__ __align__(16) __nv_bfloat16 g_Vth[Zb*Hh*DKk*Nn]; // [zh][d][key]
__device__ __align__(16) __nv_bfloat16 g_Vtl[Zb*Hh*DKk*Nn];

// ---------------- helpers ----------------
__device__ __forceinline__ uint32_t smem_u32(const void* p) {
    uint32_t a;
    asm("{ .reg .u64 t; cvta.to.shared.u64 t, %1; cvt.u32.u64 %0, t; }"
        : "=r"(a) : "l"(p));
    return a;
}
__device__ __forceinline__ void ldsm4(uint32_t addr, uint32_t* r) {
    asm volatile("ldmatrix.sync.aligned.m8n8.x4.shared.b16 {%0,%1,%2,%3}, [%4];"
                 : "=r"(r[0]), "=r"(r[1]), "=r"(r[2]), "=r"(r[3]) : "r"(addr));
}
__device__ __forceinline__ void mma16816(float* c, const uint32_t* a,
                                         const uint32_t* b) {
    asm volatile(
        "mma.sync.aligned.m16n8k16.row.col.f32.bf16.bf16.f32 "
        "{%0,%1,%2,%3}, {%4,%5,%6,%7}, {%8,%9}, {%0,%1,%2,%3};"
        : "+f"(c[0]), "+f"(c[1]), "+f"(c[2]), "+f"(c[3])
        : "r"(a[0]), "r"(a[1]), "r"(a[2]), "r"(a[3]), "r"(b[0]), "r"(b[1]));
}
__device__ __forceinline__ void cpasync16(uint32_t dst, const void* src) {
    asm volatile("cp.async.cg.shared.global [%0], [%1], 16;"
                 :: "r"(dst), "l"(src) : "memory");
}
#define CP_COMMIT()  asm volatile("cp.async.commit_group;" ::: "memory")
#define CP_WAIT1()   asm volatile("cp.async.wait_group 1;" ::: "memory")
#define CP_WAIT0()   asm volatile("cp.async.wait_group 0;" ::: "memory")

__device__ __forceinline__ uint32_t pack_bf2(float a, float b) {
    __nv_bfloat162 t = __floats2bfloat162_rn(a, b);
    return *(uint32_t*)&t;
}
__device__ __forceinline__ float bflo(float v) {
    return v - __bfloat162float(__float2bfloat16_rn(v));
}

// ---------------- mask dtype detection + expansion ----------------
__global__ void mask_kernel(const unsigned char* __restrict__ raw) {
    __shared__ int s_gt1, s_off;
    int tid = threadIdx.x;
    if (tid == 0) { s_gt1 = 0; s_off = 0; }
    __syncthreads();
    int gt1 = 0, off = 0;
    for (int i = tid; i < Tt; i += blockDim.x) {
        unsigned char b = raw[i];
        if (b > 1) gt1 = 1;
        if (b && (i & 3)) off = 1;
    }
    if (gt1) atomicOr(&s_gt1, 1);
    if (off) atomicOr(&s_off, 1);
    __syncthreads();
    int mode = s_gt1 ? 2 : (s_off ? 0 : 1);  // 0=bool, 1=int32, 2=float32
    for (int i = tid; i < Tt; i += blockDim.x) {
        int v;
        if (mode == 0)      v = (raw[i] != 0);
        else if (mode == 1) v = (((const int*)raw)[i] != 0);
        else                v = (((const float*)raw)[i] != 0.0f);
        g_mask[i] = v;
    }
}

// ---------------- fp32 -> bf16 hi/lo elementwise split ----------------
__global__ void split_kernel(const float* __restrict__ in,
                             __nv_bfloat16* __restrict__ hi,
                             __nv_bfloat16* __restrict__ lo, int n) {
    int i = blockIdx.x * blockDim.x + threadIdx.x;
    if (i < n) {
        float v = in[i];
        __nv_bfloat16 h = __float2bfloat16_rn(v);
        hi[i] = h;
        lo[i] = __float2bfloat16_rn(v - __bfloat162float(h));
    }
}

// ---------------- QKV weight transpose + split ----------------
__global__ __launch_bounds__(256) void wsplit_kernel(
    const float* __restrict__ qp, const float* __restrict__ kp,
    const float* __restrict__ vp) {
    __shared__ float s[64][68];
    int which = blockIdx.y >> 4, h = blockIdx.y & 15;
    const float* W = (which == 0 ? qp : which == 1 ? kp : vp) + h * DM * DKk;
    int d0 = blockIdx.x * 64;
    int tid = threadIdx.x;
    #pragma unroll
    for (int i = 0; i < 4; i++) {
        int idx = tid + i * 256;
        int r = idx >> 4, c4 = idx & 15;
        float4 v = *(const float4*)&W[(d0 + r) * DKk + c4 * 4];
        s[r][c4 * 4 + 0] = v.x; s[r][c4 * 4 + 1] = v.y;
        s[r][c4 * 4 + 2] = v.z; s[r][c4 * 4 + 3] = v.w;
    }
    __syncthreads();
    #pragma unroll
    for (int i = 0; i < 4; i++) {
        int idx = tid + i * 256;
        int c = idx >> 4, r4 = idx & 15;
        int n = which * 1024 + h * 64 + c;
        size_t base = (size_t)n * DM + d0 + r4 * 4;
        #pragma unroll
        for (int j = 0; j < 4; j++) {
            float v = s[r4 * 4 + j][c];
            __nv_bfloat16 hh = __float2bfloat16_rn(v);
            g_wth[base + j] = hh;
            g_wtl[base + j] = __float2bfloat16_rn(v - __bfloat162float(hh));
        }
    }
}

// ---------------- HMMA split-bf16 GEMM (validated R6 core) ----------------
#define KCH 32
#define ROWB 80
#define TILEB (128 * ROWB)
#define BUFB  (4 * TILEB)
#define GEMM_SMEM (2 * BUFB)            // 81920
#define NCHUNK (DM / KCH)

__global__ __launch_bounds__(256, 2) void gemm_bf16x3_kernel(
    const __nv_bfloat16* __restrict__ Ah, const __nv_bfloat16* __restrict__ Al,
    const __nv_bfloat16* __restrict__ Bh, const __nv_bfloat16* __restrict__ Bl,
    const float* __restrict__ qb, const float* __restrict__ kb,
    const float* __restrict__ vb, float* __restrict__ outp, int mode) {
    extern __shared__ __align__(16) char dynsm[];
    __shared__ float s_bias[128];

    int tid = threadIdx.x, wid = tid >> 5, lane = tid & 31;
    int t0 = blockIdx.x * 128, n0 = blockIdx.y * 128;
    uint32_t sbase = smem_u32(dynsm);

    if (tid < 128) {
        if (mode == 0) {
            int n = n0 + tid;
            int which = n >> 10, hd = n & 1023;
            s_bias[tid] = (which == 0 ? qb : which == 1 ? kb : vb)[hd];
        } else {
            s_bias[tid] = 0.0f;
        }
    }

    const __nv_bfloat16* bases[4] = {Ah, Al, Bh, Bl};
    auto issue_loads = [&](int c) {
        int k0 = c * KCH;
        uint32_t dbase = sbase + (c & 1) * BUFB;
        #pragma unroll
        for (int s = 0; s < 8; s++) {
            const int tile = s >> 1;
            int idx = tid + s * 256;
            int row = (idx >> 2) & 127, u = idx & 3;
            uint32_t dst = dbase + tile * TILEB + row * ROWB + u * 16;
            int grow = (tile < 2) ? (t0 + row) : (n0 + row);
            cpasync16(dst, bases[tile] + (size_t)grow * DM + k0 + u * 8);
        }
        CP_COMMIT();
    };

    float acc[4][4][4];
    #pragma unroll
    for (int i = 0; i < 4; i++)
        #pragma unroll
        for (int j = 0; j < 4; j++)
            #pragma unroll
            for (int q = 0; q < 4; q++) acc[i][j][q] = 0.0f;

    int wm = (wid >> 2) * 64;
    int wn = (wid & 3) * 32;
    int a_r = lane & 15;
    int a_k = (lane >> 4) << 3;
    int b_r = ((lane >> 4) << 3) + (lane & 7);
    int b_k = ((lane >> 3) & 1) << 3;

    issue_loads(0);

    for (int c = 0; c < NCHUNK; c++) {
        if (c + 1 < NCHUNK) { issue_loads(c + 1); CP_WAIT1(); }
        else                { CP_WAIT0(); }
        __syncthreads();

        uint32_t sb = sbase + (c & 1) * BUFB;
        uint32_t ahb = sb, alb = sb + TILEB, bhb = sb + 2 * TILEB, blb = sb + 3 * TILEB;

        #pragma unroll
        for (int ks = 0; ks < 2; ks++) {
            int k0 = ks * 16;
            uint32_t bh[2][4], bl[2][4];
            #pragma unroll
            for (int p = 0; p < 2; p++) {
                uint32_t roff = (wn + p * 16 + b_r) * ROWB + (k0 + b_k) * 2;
                ldsm4(bhb + roff, bh[p]);
                ldsm4(blb + roff, bl[p]);
            }
            #pragma unroll
            for (int mt = 0; mt < 4; mt++) {
                uint32_t ah[4], al[4];
                uint32_t roff = (wm + mt * 16 + a_r) * ROWB + (k0 + a_k) * 2;
                ldsm4(ahb + roff, ah);
                ldsm4(alb + roff, al);
                #pragma unroll
                for (int nt = 0; nt < 4; nt++) {
                    const uint32_t* bhf = &bh[nt >> 1][(nt & 1) * 2];
                    const uint32_t* blf = &bl[nt >> 1][(nt & 1) * 2];
                    mma16816(acc[mt][nt], ah, bhf);
                    mma16816(acc[mt][nt], ah, blf);
                    mma16816(acc[mt][nt], al, bhf);
                }
            }
        }
        __syncthreads();
    }

    int er = lane >> 2, ec = (lane & 3) * 2;
    #pragma unroll
    for (int mt = 0; mt < 4; mt++)
        #pragma unroll
        for (int nt = 0; nt < 4; nt++) {
            int gcol = n0 + wn + nt * 8 + ec;
            float b0 = s_bias[gcol - n0], b1 = s_bias[gcol - n0 + 1];
            #pragma unroll
            for (int half = 0; half < 2; half++) {
                int grow = t0 + wm + mt * 16 + er + half * 8;
                float vx = acc[mt][nt][half * 2 + 0] + b0;
                float vy = acc[mt][nt][half * 2 + 1] + b1;
                if (mode == 0) {
                    int which = gcol >> 10, hh = (gcol >> 6) & 15, dk = gcol & 63;
                    int z = grow >> 11, nnn = grow & (Nn - 1);
                    int zh = z * Hh + hh;
                    if (which == 0) {
                        vx *= 0.125f; vy *= 0.125f;  // fold softmax scale into Q
                        size_t o = ((size_t)zh * Nn + nnn) * DKk + dk;
                        *(uint32_t*)&g_Qh[o] = pack_bf2(vx, vy);
                        *(uint32_t*)&g_Ql[o] = pack_bf2(bflo(vx), bflo(vy));
                    } else if (which == 1) {
                        size_t o = ((size_t)zh * Nn + nnn) * DKk + dk;
                        *(uint32_t*)&g_Kh[o] = pack_bf2(vx, vy);
                        *(uint32_t*)&g_Kl[o] = pack_bf2(bflo(vx), bflo(vy));
                    } else {
                        size_t o = ((size_t)zh * DKk + dk) * Nn + nnn;
                        g_Vth[o] = __float2bfloat16_rn(vx);
                        g_Vtl[o] = __float2bfloat16_rn(bflo(vx));
                        g_Vth[o + Nn] = __float2bfloat16_rn(vy);
                        g_Vtl[o + Nn] = __float2bfloat16_rn(bflo(vy));
                    }
                } else {
                    *(float2*)&outp[(size_t)grow * DM + gcol] =
                        make_float2(vx, vy);
                }
            }
        }
}

// ---------------- HMMA flash attention ----------------
// CTA: 128 queries x (z,h); 8 warps, warp = 16 query rows (full key width).
// Key blocks of 64, double-buffered cp.async. 3-term split for S and PV.
#define AROWB 144
#define QTILE (128 * AROWB)             // 18432
#define KTILE (64 * AROWB)              // 9216
#define ABUF  (4 * KTILE)               // 36864: Kh,Kl,Vth,Vtl
#define OFF_BUF  (2 * QTILE)            // 36864
#define OFF_MASK (OFF_BUF + 2 * ABUF)   // 110592
#define ATTN_SMEM (OFF_MASK + 2048)     // 112640
#define NKB (Nn / 64)                   // 32

__global__ __launch_bounds__(256, 2) void attn_kernel() {
    extern __shared__ __align__(16) char smc[];
    int tid = threadIdx.x, wid = tid >> 5, lane = tid & 31;
    int q0 = blockIdx.x * 128;
    int h = blockIdx.y, z = blockIdx.z;
    int zh = z * Hh + h;
    const __nv_bfloat16* Qhg = g_Qh + (size_t)zh * Nn * DKk;
    const __nv_bfloat16* Qlg = g_Ql + (size_t)zh * Nn * DKk;
    const __nv_bfloat16* Khg = g_Kh + (size_t)zh * Nn * DKk;
    const __nv_bfloat16* Klg = g_Kl + (size_t)zh * Nn * DKk;
    const __nv_bfloat16* Vhg = g_Vth + (size_t)zh * DKk * Nn;
    const __nv_bfloat16* Vlg = g_Vtl + (size_t)zh * DKk * Nn;
    uint32_t sb = smem_u32(smc);

    // 4 tiles x 64 rows x 8x16B units = 2048 slots -> 8 per thread
    auto issue_kv = [&](int c) {
        int kb = c * 64;
        uint32_t dbase = sb + OFF_BUF + (c & 1) * ABUF;
        #pragma unroll
        for (int s = 0; s < 8; s++) {
            const int tile = s >> 1;            // 512 slots per tile
            int idx = tid + s * 256;
            int row = (idx >> 3) & 63, u = idx & 7;
            uint32_t dst = dbase + tile * KTILE + row * AROWB + u * 16;
            const __nv_bfloat16* src;
            if (tile == 0)      src = Khg + (size_t)(kb + row) * DKk + u * 8;
            else if (tile == 1) src = Klg + (size_t)(kb + row) * DKk + u * 8;
            else if (tile == 2) src = Vhg + (size_t)row * Nn + kb + u * 8;
            else                src = Vlg + (size_t)row * Nn + kb + u * 8;
            cpasync16(dst, src);
        }
        CP_COMMIT();
    };

    // Q tiles (hi/lo): 2 tiles x 128 rows x 8 units = 2048 slots -> 8/thread
    #pragma unroll
    for (int s = 0; s < 8; s++) {
        int idx = tid + s * 256;
        int tile = idx >> 10, rr = (idx >> 3) & 127, uu = idx & 7;
        uint32_t dst = sb + tile * QTILE + rr * AROWB + uu * 16;
        const __nv_bfloat16* src = (tile == 0 ? Qhg : Qlg) +
                                   (size_t)(q0 + rr) * DKk + uu * 8;
        cpasync16(dst, src);
    }
    issue_kv(0);            // commits: group0 = Q + KV0
    issue_kv(1);            // group1 = KV1
    // key mask for this z -> smem chars
    {
        char* msk = smc + OFF_MASK;
        #pragma unroll
        for (int s = 0; s < 8; s++) {
            int i = tid + s * 256;
            msk[i] = (char)g_mask[z * Nn + i];
        }
    }
    CP_WAIT1();             // group0 done (Q + KV0)
    __syncthreads();

    float O[8][4];
    #pragma unroll
    for (int i = 0; i < 8; i++)
        #pragma unroll
        for (int j = 0; j < 4; j++) O[i][j] = 0.0f;
    float m0 = -1e30f, m1 = -1e30f, l0 = 0.0f, l1 = 0.0f;

    int er = lane >> 2, ec = (lane & 3) * 2;
    int a_r = lane & 15;
    int a_k = (lane >> 4) << 3;
    int b_r = ((lane >> 4) << 3) + (lane & 7);
    int b_k = ((lane >> 3) & 1) << 3;
    const char* msk = smc + OFF_MASK;

    for (int c = 0; c < NKB; c++) {
        uint32_t bb = sb + OFF_BUF + (c & 1) * ABUF;
        uint32_t khb = bb, klb = bb + KTILE, vhb = bb + 2 * KTILE, vlb = bb + 3 * KTILE;

        // ---- S = Q K^T (3-term), S tile 16q x 64k per warp ----
        float s[8][4];
        #pragma unroll
        for (int i = 0; i < 8; i++)
            #pragma unroll
            for (int j = 0; j < 4; j++) s[i][j] = 0.0f;

        #pragma unroll
        for (int ks = 0; ks < 4; ks++) {
            uint32_t ah[4], al[4];
            uint32_t roffA = (wid * 16 + a_r) * AROWB + (ks * 16 + a_k) * 2;
            ldsm4(sb + roffA, ah);           // Qh at offset 0
            ldsm4(sb + QTILE + roffA, al);   // Ql
            #pragma unroll
            for (int p = 0; p < 4; p++) {
                uint32_t bh[4], bl[4];
                uint32_t roffB = (p * 16 + b_r) * AROWB + (ks * 16 + b_k) * 2;
                ldsm4(khb + roffB, bh);
                ldsm4(klb + roffB, bl);
                #pragma unroll
                for (int q2 = 0; q2 < 2; q2++) {
                    int nt = 2 * p + q2;
                    mma16816(s[nt], ah, &bh[q2 * 2]);
                    mma16816(s[nt], ah, &bl[q2 * 2]);
                    mma16816(s[nt], al, &bh[q2 * 2]);
                }
            }
        }

        // ---- mask (Q pre-scaled; masked = exact -1e9 like reference) ----
        #pragma unroll
        for (int nt = 0; nt < 8; nt++) {
            int k = c * 64 + nt * 8 + ec;
            if (!msk[k])     { s[nt][0] = -1e9f; s[nt][2] = -1e9f; }
            if (!msk[k + 1]) { s[nt][1] = -1e9f; s[nt][3] = -1e9f; }
        }

        // ---- online softmax (rows er, er+8 of warp tile; quad-shared) ----
        float tm0 = -1e30f, tm1 = -1e30f;
        #pragma unroll
        for (int nt = 0; nt < 8; nt++) {
            tm0 = fmaxf(tm0, fmaxf(s[nt][0], s[nt][1]));
            tm1 = fmaxf(tm1, fmaxf(s[nt][2], s[nt][3]));
        }
        tm0 = fmaxf(tm0, __shfl_xor_sync(0xffffffffu, tm0, 1));
        tm0 = fmaxf(tm0, __shfl_xor_sync(0xffffffffu, tm0, 2));
        tm1 = fmaxf(tm1, __shfl_xor_sync(0xffffffffu, tm1, 1));
        tm1 = fmaxf(tm1, __shfl_xor_sync(0xffffffffu, tm1, 2));
        float mn0 = fmaxf(m0, tm0), mn1 = fmaxf(m1, tm1);
        float f0 = __expf(m0 - mn0), f1 = __expf(m1 - mn1);
        float ps0 = 0.0f, ps1 = 0.0f;
        #pragma unroll
        for (int nt = 0; nt < 8; nt++) {
            s[nt][0] = __expf(s[nt][0] - mn0); ps0 += s[nt][0];
            s[nt][1] = __expf(s[nt][1] - mn0); ps0 += s[nt][1];
            s[nt][2] = __expf(s[nt][2] - mn1); ps1 += s[nt][2];
            s[nt][3] = __expf(s[nt][3] - mn1); ps1 += s[nt][3];
        }
        ps0 += __shfl_xor_sync(0xffffffffu, ps0, 1);
        ps0 += __shfl_xor_sync(0xffffffffu, ps0, 2);
        ps1 += __shfl_xor_sync(0xffffffffu, ps1, 1);
        ps1 += __shfl_xor_sync(0xffffffffu, ps1, 2);
        l0 = l0 * f0 + ps0; m0 = mn0;
        l1 = l1 * f1 + ps1; m1 = mn1;
        #pragma unroll
        for (int nt = 0; nt < 8; nt++) {
            O[nt][0] *= f0; O[nt][1] *= f0;
            O[nt][2] *= f1; O[nt][3] *= f1;
        }

        // ---- O += P V (3-term): A = P from S-frags (register repack) ----
        #pragma unroll
        for (int ks = 0; ks < 4; ks++) {
            float c0 = s[2*ks][0], c1 = s[2*ks][1], c2 = s[2*ks][2], c3 = s[2*ks][3];
            float d0 = s[2*ks+1][0], d1 = s[2*ks+1][1], d2 = s[2*ks+1][2], d3 = s[2*ks+1][3];
            uint32_t ph[4], pl[4];
            ph[0] = pack_bf2(c0, c1); ph[1] = pack_bf2(c2, c3);
            ph[2] = pack_bf2(d0, d1); ph[3] = pack_bf2(d2, d3);
            pl[0] = pack_bf2(bflo(c0), bflo(c1)); pl[1] = pack_bf2(bflo(c2), bflo(c3));
            pl[2] = pack_bf2(bflo(d0), bflo(d1)); pl[3] = pack_bf2(bflo(d2), bflo(d3));
            #pragma unroll
            for (int p = 0; p < 4; p++) {
                uint32_t bh[4], bl[4];
                uint32_t roffB = (p * 16 + b_r) * AROWB + (ks * 16 + b_k) * 2;
                ldsm4(vhb + roffB, bh);
                ldsm4(vlb + roffB, bl);
                #pragma unroll
                for (int q2 = 0; q2 < 2; q2++) {
                    int nt = 2 * p + q2;
                    mma16816(O[nt], ph, &bh[q2 * 2]);
                    mma16816(O[nt], ph, &bl[q2 * 2]);
                    mma16816(O[nt], pl, &bh[q2 * 2]);
                }
            }
        }

        __syncthreads();                        // all warps done with buf c&1
        if (c + 2 < NKB) issue_kv(c + 2);       // refill buf c&1
        if (c + 1 < NKB) {
            if (c + 2 < NKB) CP_WAIT1(); else CP_WAIT0();  // tail: drain fully
            __syncthreads();
        }
    }

    // ---- epilogue: normalize, query-mask zero, write ctx hi/lo ----
    int qr0 = q0 + wid * 16 + er, qr1 = qr0 + 8;
    float inv0 = g_mask[z * Nn + qr0] ? (1.0f / l0) : 0.0f;
    float inv1 = g_mask[z * Nn + qr1] ? (1.0f / l1) : 0.0f;
    #pragma unroll
    for (int nt = 0; nt < 8; nt++) {
        int d = nt * 8 + ec;
        float v0 = O[nt][0] * inv0, v1 = O[nt][1] * inv0;
        float w0 = O[nt][2] * inv1, w1 = O[nt][3] * inv1;
        size_t o0 = (size_t)(z * Nn + qr0) * DM + h * DKk + d;
        size_t o1 = (size_t)(z * Nn + qr1) * DM + h * DKk + d;
        *(uint32_t*)&g_ctxh[o0] = pack_bf2(v0, v1);
        *(uint32_t*)&g_ctxl[o0] = pack_bf2(bflo(v0), bflo(v1));
        *(uint32_t*)&g_ctxh[o1] = pack_bf2(w0, w1);
        *(uint32_t*)&g_ctxl[o1] = pack_bf2(bflo(w0), bflo(w1));
    }
}

// ---------------- launch ----------------
extern "C" void kernel_launch(void* const* d_in, const int* in_sizes, int n_in,
                              void* d_out, int out_size) {
    const float* x  = (const float*)d_in[0];
    const unsigned char* mraw = (const unsigned char*)d_in[1];
    const float* qp = (const float*)d_in[2];
    const float* kp = (const float*)d_in[3];
    const float* vp = (const float*)d_in[4];
    const float* qb = (const float*)d_in[5];
    const float* kb = (const float*)d_in[6];
    const float* vb = (const float*)d_in[7];
    const float* ow = (const float*)d_in[8];
    float* out = (float*)d_out;

    __nv_bfloat16 *xh_p, *xl_p, *wth_p, *wtl_p, *woh_p, *wol_p, *ctxh_p, *ctxl_p;
    cudaGetSymbolAddress((void**)&xh_p,  g_xh);
    cudaGetSymbolAddress((void**)&xl_p,  g_xl);
    cudaGetSymbolAddress((void**)&wth_p, g_wth);
    cudaGetSymbolAddress((void**)&wtl_p, g_wtl);
    cudaGetSymbolAddress((void**)&woh_p, g_woh);
    cudaGetSymbolAddress((void**)&wol_p, g_wol);
    cudaGetSymbolAddress((void**)&ctxh_p, g_ctxh);
    cudaGetSymbolAddress((void**)&ctxl_p, g_ctxl);
    cudaFuncSetAttribute(attn_kernel,
                         cudaFuncAttributeMaxDynamicSharedMemorySize, ATTN_SMEM);
    cudaFuncSetAttribute(gemm_bf16x3_kernel,
                         cudaFuncAttributeMaxDynamicSharedMemorySize, GEMM_SMEM);

    mask_kernel<<<1, 256>>>(mraw);
    split_kernel<<<(Tt * DM) / 256, 256>>>(x, xh_p, xl_p, Tt * DM);
    wsplit_kernel<<<dim3(DM / 64, 3 * Hh), 256>>>(qp, kp, vp);
    split_kernel<<<(DM * DM) / 256, 256>>>(ow, woh_p, wol_p, DM * DM);

    // QKV: A = x (hi/lo), B = wt [3072][1024]; epilogue emits Q/K/V bf16 hi/lo
    gemm_bf16x3_kernel<<<dim3(Tt / 128, 3 * Hh * DKk / 128), 256, GEMM_SMEM>>>(
        xh_p, xl_p, wth_p, wtl_p, qb, kb, vb, nullptr, 0);

    attn_kernel<<<dim3(Nn / 128, Hh, Zb), 256, ATTN_SMEM>>>();

    // out-proj: A = ctx (hi/lo), B = Wo [1024][1024]
    gemm_bf16x3_kernel<<<dim3(Tt / 128, DM / 128), 256, GEMM_SMEM>>>(
        ctxh_p, ctxl_p, woh_p, wol_p, nullptr, nullptr, nullptr, out, 1);
}

// round 14
// speedup vs baseline: 3.5197x; 1.7957x over previous
#include <cuda_runtime.h>
#include <cuda_fp16.h>
#include <stdint.h>
#include <math.h>

#define Zb 2
#define Nn 2048
#define DM 1024
#define Hh 16
#define DKk 64
#define Tt (Zb*Nn)   // 4096

// ---------------- scratch (no allocations allowed) ----------------
__device__ int g_mask[Tt];
// fp16 hi/lo split operands
__device__ __align__(16) __half g_xh[Tt*DM];
__device__ __align__(16) __half g_xl[Tt*DM];
__device__ __align__(16) __half g_wth[3*Hh*DKk*DM];  // [n=3072][k=1024]
__device__ __align__(16) __half g_wtl[3*Hh*DKk*DM];
__device__ __align__(16) __half g_woh[DM*DM];        // [n][k]
__device__ __align__(16) __half g_wol[DM*DM];
__device__ __align__(16) __half g_ctxh[Tt*DM];
__device__ __align__(16) __half g_ctxl[Tt*DM];
// attention operands (Q pre-scaled by 0.125)
__device__ __align__(16) __half g_Qh[Zb*Hh*Nn*DKk];  // [zh][q][d]
__device__ __align__(16) __half g_Ql[Zb*Hh*Nn*DKk];
__device__ __align__(16) __half g_Kh[Zb*Hh*Nn*DKk];  // [zh][key][d]
__device__ __align__(16) __half g_Kl[Zb*Hh*Nn*DKk];
__device__ __align__(16) __half g_Vh[Zb*Hh*DKk*Nn];  // [zh][d][key] hi only

// ---------------- helpers ----------------
__device__ __forceinline__ uint32_t smem_u32(const void* p) {
    uint32_t a;
    asm("{ .reg .u64 t; cvta.to.shared.u64 t, %1; cvt.u32.u64 %0, t; }"
        : "=r"(a) : "l"(p));
    return a;
}
__device__ __forceinline__ void ldsm4(uint32_t addr, uint32_t* r) {
    asm volatile("ldmatrix.sync.aligned.m8n8.x4.shared.b16 {%0,%1,%2,%3}, [%4];"
                 : "=r"(r[0]), "=r"(r[1]), "=r"(r[2]), "=r"(r[3]) : "r"(addr));
}
__device__ __forceinline__ void mma16816(float* c, const uint32_t* a,
                                         const uint32_t* b) {
    asm volatile(
        "mma.sync.aligned.m16n8k16.row.col.f32.f16.f16.f32 "
        "{%0,%1,%2,%3}, {%4,%5,%6,%7}, {%8,%9}, {%0,%1,%2,%3};"
        : "+f"(c[0]), "+f"(c[1]), "+f"(c[2]), "+f"(c[3])
        : "r"(a[0]), "r"(a[1]), "r"(a[2]), "r"(a[3]), "r"(b[0]), "r"(b[1]));
}
__device__ __forceinline__ void cpasync16(uint32_t dst, const void* src) {
    asm volatile("cp.async.cg.shared.global [%0], [%1], 16;"
                 :: "r"(dst), "l"(src) : "memory");
}
#define CP_COMMIT()  asm volatile("cp.async.commit_group;" ::: "memory")
#define CP_WAIT1()   asm volatile("cp.async.wait_group 1;" ::: "memory")
#define CP_WAIT0()   asm volatile("cp.async.wait_group 0;" ::: "memory")

__device__ __forceinline__ uint32_t pack_hf2(float a, float b) {
    __half2 t = __floats2half2_rn(a, b);
    return *(uint32_t*)&t;
}
__device__ __forceinline__ float hflo(float v) {
    return v - __half2float(__float2half_rn(v));
}

// ---------------- mask dtype detection + expansion ----------------
__global__ void mask_kernel(const unsigned char* __restrict__ raw) {
    __shared__ int s_gt1, s_off;
    int tid = threadIdx.x;
    if (tid == 0) { s_gt1 = 0; s_off = 0; }
    __syncthreads();
    int gt1 = 0, off = 0;
    for (int i = tid; i < Tt; i += blockDim.x) {
        unsigned char b = raw[i];
        if (b > 1) gt1 = 1;
        if (b && (i & 3)) off = 1;
    }
    if (gt1) atomicOr(&s_gt1, 1);
    if (off) atomicOr(&s_off, 1);
    __syncthreads();
    int mode = s_gt1 ? 2 : (s_off ? 0 : 1);  // 0=bool, 1=int32, 2=float32
    for (int i = tid; i < Tt; i += blockDim.x) {
        int v;
        if (mode == 0)      v = (raw[i] != 0);
        else if (mode == 1) v = (((const int*)raw)[i] != 0);
        else                v = (((const float*)raw)[i] != 0.0f);
        g_mask[i] = v;
    }
}

// ---------------- fp32 -> fp16 hi/lo elementwise split ----------------
__global__ void split_kernel(const float* __restrict__ in,
                             __half* __restrict__ hi,
                             __half* __restrict__ lo, int n) {
    int i = blockIdx.x * blockDim.x + threadIdx.x;
    if (i < n) {
        float v = in[i];
        __half h = __float2half_rn(v);
        hi[i] = h;
        lo[i] = __float2half_rn(v - __half2float(h));
    }
}

// ---------------- QKV weight transpose + split ----------------
__global__ __launch_bounds__(256) void wsplit_kernel(
    const float* __restrict__ qp, const float* __restrict__ kp,
    const float* __restrict__ vp) {
    __shared__ float s[64][68];
    int which = blockIdx.y >> 4, h = blockIdx.y & 15;
    const float* W = (which == 0 ? qp : which == 1 ? kp : vp) + h * DM * DKk;
    int d0 = blockIdx.x * 64;
    int tid = threadIdx.x;
    #pragma unroll
    for (int i = 0; i < 4; i++) {
        int idx = tid + i * 256;
        int r = idx >> 4, c4 = idx & 15;
        float4 v = *(const float4*)&W[(d0 + r) * DKk + c4 * 4];
        s[r][c4 * 4 + 0] = v.x; s[r][c4 * 4 + 1] = v.y;
        s[r][c4 * 4 + 2] = v.z; s[r][c4 * 4 + 3] = v.w;
    }
    __syncthreads();
    #pragma unroll
    for (int i = 0; i < 4; i++) {
        int idx = tid + i * 256;
        int c = idx >> 4, r4 = idx & 15;
        int n = which * 1024 + h * 64 + c;
        size_t base = (size_t)n * DM + d0 + r4 * 4;
        #pragma unroll
        for (int j = 0; j < 4; j++) {
            float v = s[r4 * 4 + j][c];
            __half hh = __float2half_rn(v);
            g_wth[base + j] = hh;
            g_wtl[base + j] = __float2half_rn(v - __half2float(hh));
        }
    }
}

// ---------------- HMMA split-fp16 GEMM (validated R6 core, fp16) ----------------
#define KCH 32
#define ROWB 80
#define TILEB (128 * ROWB)
#define BUFB  (4 * TILEB)
#define GEMM_SMEM (2 * BUFB)            // 81920
#define NCHUNK (DM / KCH)

__global__ __launch_bounds__(256, 2) void gemm_fp16x3_kernel(
    const __half* __restrict__ Ah, const __half* __restrict__ Al,
    const __half* __restrict__ Bh, const __half* __restrict__ Bl,
    const float* __restrict__ qb, const float* __restrict__ kb,
    const float* __restrict__ vb, float* __restrict__ outp, int mode) {
    extern __shared__ __align__(16) char dynsm[];
    __shared__ float s_bias[128];

    int tid = threadIdx.x, wid = tid >> 5, lane = tid & 31;
    int t0 = blockIdx.x * 128, n0 = blockIdx.y * 128;
    uint32_t sbase = smem_u32(dynsm);

    if (tid < 128) {
        if (mode == 0) {
            int n = n0 + tid;
            int which = n >> 10, hd = n & 1023;
            s_bias[tid] = (which == 0 ? qb : which == 1 ? kb : vb)[hd];
        } else {
            s_bias[tid] = 0.0f;
        }
    }

    const __half* bases[4] = {Ah, Al, Bh, Bl};
    auto issue_loads = [&](int c) {
        int k0 = c * KCH;
        uint32_t dbase = sbase + (c & 1) * BUFB;
        #pragma unroll
        for (int s = 0; s < 8; s++) {
            const int tile = s >> 1;
            int idx = tid + s * 256;
            int row = (idx >> 2) & 127, u = idx & 3;
            uint32_t dst = dbase + tile * TILEB + row * ROWB + u * 16;
            int grow = (tile < 2) ? (t0 + row) : (n0 + row);
            cpasync16(dst, bases[tile] + (size_t)grow * DM + k0 + u * 8);
        }
        CP_COMMIT();
    };

    float acc[4][4][4];
    #pragma unroll
    for (int i = 0; i < 4; i++)
        #pragma unroll
        for (int j = 0; j < 4; j++)
            #pragma unroll
            for (int q = 0; q < 4; q++) acc[i][j][q] = 0.0f;

    int wm = (wid >> 2) * 64;
    int wn = (wid & 3) * 32;
    int a_r = lane & 15;
    int a_k = (lane >> 4) << 3;
    int b_r = ((lane >> 4) << 3) + (lane & 7);
    int b_k = ((lane >> 3) & 1) << 3;

    issue_loads(0);

    for (int c = 0; c < NCHUNK; c++) {
        if (c + 1 < NCHUNK) { issue_loads(c + 1); CP_WAIT1(); }
        else                { CP_WAIT0(); }
        __syncthreads();

        uint32_t sb = sbase + (c & 1) * BUFB;
        uint32_t ahb = sb, alb = sb + TILEB, bhb = sb + 2 * TILEB, blb = sb + 3 * TILEB;

        #pragma unroll
        for (int ks = 0; ks < 2; ks++) {
            int k0 = ks * 16;
            uint32_t bh[2][4], bl[2][4];
            #pragma unroll
            for (int p = 0; p < 2; p++) {
                uint32_t roff = (wn + p * 16 + b_r) * ROWB + (k0 + b_k) * 2;
                ldsm4(bhb + roff, bh[p]);
                ldsm4(blb + roff, bl[p]);
            }
            #pragma unroll
            for (int mt = 0; mt < 4; mt++) {
                uint32_t ah[4], al[4];
                uint32_t roff = (wm + mt * 16 + a_r) * ROWB + (k0 + a_k) * 2;
                ldsm4(ahb + roff, ah);
                ldsm4(alb + roff, al);
                #pragma unroll
                for (int nt = 0; nt < 4; nt++) {
                    const uint32_t* bhf = &bh[nt >> 1][(nt & 1) * 2];
                    const uint32_t* blf = &bl[nt >> 1][(nt & 1) * 2];
                    mma16816(acc[mt][nt], ah, bhf);
                    mma16816(acc[mt][nt], ah, blf);
                    mma16816(acc[mt][nt], al, bhf);
                }
            }
        }
        __syncthreads();
    }

    int er = lane >> 2, ec = (lane & 3) * 2;
    #pragma unroll
    for (int mt = 0; mt < 4; mt++)
        #pragma unroll
        for (int nt = 0; nt < 4; nt++) {
            int gcol = n0 + wn + nt * 8 + ec;
            float b0 = s_bias[gcol - n0], b1 = s_bias[gcol - n0 + 1];
            #pragma unroll
            for (int half = 0; half < 2; half++) {
                int grow = t0 + wm + mt * 16 + er + half * 8;
                float vx = acc[mt][nt][half * 2 + 0] + b0;
                float vy = acc[mt][nt][half * 2 + 1] + b1;
                if (mode == 0) {
                    int which = gcol >> 10, hh = (gcol >> 6) & 15, dk = gcol & 63;
                    int z = grow >> 11, nnn = grow & (Nn - 1);
                    int zh = z * Hh + hh;
                    if (which == 0) {
                        vx *= 0.125f; vy *= 0.125f;  // fold softmax scale into Q
                        size_t o = ((size_t)zh * Nn + nnn) * DKk + dk;
                        *(uint32_t*)&g_Qh[o] = pack_hf2(vx, vy);
                        *(uint32_t*)&g_Ql[o] = pack_hf2(hflo(vx), hflo(vy));
                    } else if (which == 1) {
                        size_t o = ((size_t)zh * Nn + nnn) * DKk + dk;
                        *(uint32_t*)&g_Kh[o] = pack_hf2(vx, vy);
                        *(uint32_t*)&g_Kl[o] = pack_hf2(hflo(vx), hflo(vy));
                    } else {
                        size_t o = ((size_t)zh * DKk + dk) * Nn + nnn;
                        g_Vh[o] = __float2half_rn(vx);
                        g_Vh[o + Nn] = __float2half_rn(vy);
                    }
                } else {
                    *(float2*)&outp[(size_t)grow * DM + gcol] =
                        make_float2(vx, vy);
                }
            }
        }
}

// ---------------- HMMA flash attention (fp16; PV single-term) ----------------
// CTA: 128 queries x (z,h); 8 warps, warp = 16 query rows (full key width).
// Key blocks of 64, double-buffered cp.async. S = 3-term; PV = Ph*Vh only.
#define AROWB 144
#define QTILE (128 * AROWB)             // 18432
#define KTILE (64 * AROWB)              // 9216
#define ABUF  (3 * KTILE)               // 27648: Kh, Kl, Vh
#define OFF_BUF  (2 * QTILE)            // 36864
#define OFF_MASK (OFF_BUF + 2 * ABUF)   // 92160
#define ATTN_SMEM (OFF_MASK + 2048)     // 94208
#define NKB (Nn / 64)                   // 32

__global__ __launch_bounds__(256, 2) void attn_kernel() {
    extern __shared__ __align__(16) char smc[];
    int tid = threadIdx.x, wid = tid >> 5, lane = tid & 31;
    int q0 = blockIdx.x * 128;
    int h = blockIdx.y, z = blockIdx.z;
    int zh = z * Hh + h;
    const __half* Qhg = g_Qh + (size_t)zh * Nn * DKk;
    const __half* Qlg = g_Ql + (size_t)zh * Nn * DKk;
    const __half* Khg = g_Kh + (size_t)zh * Nn * DKk;
    const __half* Klg = g_Kl + (size_t)zh * Nn * DKk;
    const __half* Vhg = g_Vh + (size_t)zh * DKk * Nn;
    uint32_t sb = smem_u32(smc);

    // 3 tiles x 64 rows x 8x16B units = 1536 slots -> 6 per thread
    auto issue_kv = [&](int c) {
        int kb = c * 64;
        uint32_t dbase = sb + OFF_BUF + (c & 1) * ABUF;
        #pragma unroll
        for (int s = 0; s < 6; s++) {
            const int tile = s >> 1;            // 512 slots per tile
            int idx = tid + s * 256;
            int row = (idx >> 3) & 63, u = idx & 7;
            uint32_t dst = dbase + tile * KTILE + row * AROWB + u * 16;
            const __half* src;
            if (tile == 0)      src = Khg + (size_t)(kb + row) * DKk + u * 8;
            else if (tile == 1) src = Klg + (size_t)(kb + row) * DKk + u * 8;
            else                src = Vhg + (size_t)row * Nn + kb + u * 8;
            cpasync16(dst, src);
        }
        CP_COMMIT();
    };

    // Q tiles (hi/lo): 2 tiles x 128 rows x 8 units = 2048 slots -> 8/thread
    #pragma unroll
    for (int s = 0; s < 8; s++) {
        int idx = tid + s * 256;
        int tile = idx >> 10, rr = (idx >> 3) & 127, uu = idx & 7;
        uint32_t dst = sb + tile * QTILE + rr * AROWB + uu * 16;
        const __half* src = (tile == 0 ? Qhg : Qlg) +
                            (size_t)(q0 + rr) * DKk + uu * 8;
        cpasync16(dst, src);
    }
    issue_kv(0);            // commits: group0 = Q + KV0
    issue_kv(1);            // group1 = KV1
    // key mask for this z -> smem chars
    {
        char* msk = smc + OFF_MASK;
        #pragma unroll
        for (int s = 0; s < 8; s++) {
            int i = tid + s * 256;
            msk[i] = (char)g_mask[z * Nn + i];
        }
    }
    CP_WAIT1();             // group0 done (Q + KV0)
    __syncthreads();

    float O[8][4];
    #pragma unroll
    for (int i = 0; i < 8; i++)
        #pragma unroll
        for (int j = 0; j < 4; j++) O[i][j] = 0.0f;
    float m0 = -1e30f, m1 = -1e30f, l0 = 0.0f, l1 = 0.0f;  // l: per-lane partials

    int er = lane >> 2, ec = (lane & 3) * 2;
    int a_r = lane & 15;
    int a_k = (lane >> 4) << 3;
    int b_r = ((lane >> 4) << 3) + (lane & 7);
    int b_k = ((lane >> 3) & 1) << 3;
    const char* msk = smc + OFF_MASK;

    for (int c = 0; c < NKB; c++) {
        uint32_t bb = sb + OFF_BUF + (c & 1) * ABUF;
        uint32_t khb = bb, klb = bb + KTILE, vhb = bb + 2 * KTILE;

        // ---- S = Q K^T (3-term), S tile 16q x 64k per warp ----
        float s[8][4];
        #pragma unroll
        for (int i = 0; i < 8; i++)
            #pragma unroll
            for (int j = 0; j < 4; j++) s[i][j] = 0.0f;

        #pragma unroll
        for (int ks = 0; ks < 4; ks++) {
            uint32_t ah[4], al[4];
            uint32_t roffA = (wid * 16 + a_r) * AROWB + (ks * 16 + a_k) * 2;
            ldsm4(sb + roffA, ah);           // Qh at offset 0
            ldsm4(sb + QTILE + roffA, al);   // Ql
            #pragma unroll
            for (int p = 0; p < 4; p++) {
                uint32_t bh[4], bl[4];
                uint32_t roffB = (p * 16 + b_r) * AROWB + (ks * 16 + b_k) * 2;
                ldsm4(khb + roffB, bh);
                ldsm4(klb + roffB, bl);
                #pragma unroll
                for (int q2 = 0; q2 < 2; q2++) {
                    int nt = 2 * p + q2;
                    mma16816(s[nt], ah, &bh[q2 * 2]);
                    mma16816(s[nt], ah, &bl[q2 * 2]);
                    mma16816(s[nt], al, &bh[q2 * 2]);
                }
            }
        }

        // ---- mask (Q pre-scaled; masked = exact -1e9 like reference) ----
        #pragma unroll
        for (int nt = 0; nt < 8; nt++) {
            int k = c * 64 + nt * 8 + ec;
            if (!msk[k])     { s[nt][0] = -1e9f; s[nt][2] = -1e9f; }
            if (!msk[k + 1]) { s[nt][1] = -1e9f; s[nt][3] = -1e9f; }
        }

        // ---- online softmax; l kept as per-lane partial (reduced at end) ----
        float tm0 = -1e30f, tm1 = -1e30f;
        #pragma unroll
        for (int nt = 0; nt < 8; nt++) {
            tm0 = fmaxf(tm0, fmaxf(s[nt][0], s[nt][1]));
            tm1 = fmaxf(tm1, fmaxf(s[nt][2], s[nt][3]));
        }
        tm0 = fmaxf(tm0, __shfl_xor_sync(0xffffffffu, tm0, 1));
        tm0 = fmaxf(tm0, __shfl_xor_sync(0xffffffffu, tm0, 2));
        tm1 = fmaxf(tm1, __shfl_xor_sync(0xffffffffu, tm1, 1));
        tm1 = fmaxf(tm1, __shfl_xor_sync(0xffffffffu, tm1, 2));
        float mn0 = fmaxf(m0, tm0), mn1 = fmaxf(m1, tm1);
        float f0 = __expf(m0 - mn0), f1 = __expf(m1 - mn1);
        float ps0 = 0.0f, ps1 = 0.0f;
        #pragma unroll
        for (int nt = 0; nt < 8; nt++) {
            s[nt][0] = __expf(s[nt][0] - mn0); ps0 += s[nt][0];
            s[nt][1] = __expf(s[nt][1] - mn0); ps0 += s[nt][1];
            s[nt][2] = __expf(s[nt][2] - mn1); ps1 += s[nt][2];
            s[nt][3] = __expf(s[nt][3] - mn1); ps1 += s[nt][3];
        }
        l0 = l0 * f0 + ps0; m0 = mn0;   // lane-partial sums; no shuffle here
        l1 = l1 * f1 + ps1; m1 = mn1;
        #pragma unroll
        for (int nt = 0; nt < 8; nt++) {
            O[nt][0] *= f0; O[nt][1] *= f0;
            O[nt][2] *= f1; O[nt][3] *= f1;
        }

        // ---- O += P Vh (single term): A = P from S-frags (register repack) ----
        #pragma unroll
        for (int ks = 0; ks < 4; ks++) {
            uint32_t ph[4];
            ph[0] = pack_hf2(s[2*ks][0], s[2*ks][1]);
            ph[1] = pack_hf2(s[2*ks][2], s[2*ks][3]);
            ph[2] = pack_hf2(s[2*ks+1][0], s[2*ks+1][1]);
            ph[3] = pack_hf2(s[2*ks+1][2], s[2*ks+1][3]);
            #pragma unroll
            for (int p = 0; p < 4; p++) {
                uint32_t bh[4];
                uint32_t roffB = (p * 16 + b_r) * AROWB + (ks * 16 + b_k) * 2;
                ldsm4(vhb + roffB, bh);
                #pragma unroll
                for (int q2 = 0; q2 < 2; q2++) {
                    mma16816(O[2 * p + q2], ph, &bh[q2 * 2]);
                }
            }
        }

        __syncthreads();                        // all warps done with buf c&1
        if (c + 2 < NKB) issue_kv(c + 2);       // refill buf c&1
        if (c + 1 < NKB) {
            if (c + 2 < NKB) CP_WAIT1(); else CP_WAIT0();  // tail: drain fully
            __syncthreads();
        }
    }

    // ---- epilogue: reduce l partials, normalize, query-mask, write ctx ----
    l0 += __shfl_xor_sync(0xffffffffu, l0, 1);
    l0 += __shfl_xor_sync(0xffffffffu, l0, 2);
    l1 += __shfl_xor_sync(0xffffffffu, l1, 1);
    l1 += __shfl_xor_sync(0xffffffffu, l1, 2);
    int qr0 = q0 + wid * 16 + er, qr1 = qr0 + 8;
    float inv0 = g_mask[z * Nn + qr0] ? (1.0f / l0) : 0.0f;
    float inv1 = g_mask[z * Nn + qr1] ? (1.0f / l1) : 0.0f;
    #pragma unroll
    for (int nt = 0; nt < 8; nt++) {
        int d = nt * 8 + ec;
        float v0 = O[nt][0] * inv0, v1 = O[nt][1] * inv0;
        float w0 = O[nt][2] * inv1, w1 = O[nt][3] * inv1;
        size_t o0 = (size_t)(z * Nn + qr0) * DM + h * DKk + d;
        size_t o1 = (size_t)(z * Nn + qr1) * DM + h * DKk + d;
        *(uint32_t*)&g_ctxh[o0] = pack_hf2(v0, v1);
        *(uint32_t*)&g_ctxl[o0] = pack_hf2(hflo(v0), hflo(v1));
        *(uint32_t*)&g_ctxh[o1] = pack_hf2(w0, w1);
        *(uint32_t*)&g_ctxl[o1] = pack_hf2(hflo(w0), hflo(w1));
    }
}

// ---------------- launch ----------------
extern "C" void kernel_launch(void* const* d_in, const int* in_sizes, int n_in,
                              void* d_out, int out_size) {
    const float* x  = (const float*)d_in[0];
    const unsigned char* mraw = (const unsigned char*)d_in[1];
    const float* qp = (const float*)d_in[2];
    const float* kp = (const float*)d_in[3];
    const float* vp = (const float*)d_in[4];
    const float* qb = (const float*)d_in[5];
    const float* kb = (const float*)d_in[6];
    const float* vb = (const float*)d_in[7];
    const float* ow = (const float*)d_in[8];
    float* out = (float*)d_out;

    __half *xh_p, *xl_p, *wth_p, *wtl_p, *woh_p, *wol_p, *ctxh_p, *ctxl_p;
    cudaGetSymbolAddress((void**)&xh_p,  g_xh);
    cudaGetSymbolAddress((void**)&xl_p,  g_xl);
    cudaGetSymbolAddress((void**)&wth_p, g_wth);
    cudaGetSymbolAddress((void**)&wtl_p, g_wtl);
    cudaGetSymbolAddress((void**)&woh_p, g_woh);
    cudaGetSymbolAddress((void**)&wol_p, g_wol);
    cudaGetSymbolAddress((void**)&ctxh_p, g_ctxh);
    cudaGetSymbolAddress((void**)&ctxl_p, g_ctxl);
    cudaFuncSetAttribute(attn_kernel,
                         cudaFuncAttributeMaxDynamicSharedMemorySize, ATTN_SMEM);
    cudaFuncSetAttribute(gemm_fp16x3_kernel,
                         cudaFuncAttributeMaxDynamicSharedMemorySize, GEMM_SMEM);

    mask_kernel<<<1, 256>>>(mraw);
    split_kernel<<<(Tt * DM) / 256, 256>>>(x, xh_p, xl_p, Tt * DM);
    wsplit_kernel<<<dim3(DM / 64, 3 * Hh), 256>>>(qp, kp, vp);
    split_kernel<<<(DM * DM) / 256, 256>>>(ow, woh_p, wol_p, DM * DM);

    // QKV: A = x (hi/lo), B = wt [3072][1024]; epilogue emits Q/K hi/lo + Vh
    gemm_fp16x3_kernel<<<dim3(Tt / 128, 3 * Hh * DKk / 128), 256, GEMM_SMEM>>>(
        xh_p, xl_p, wth_p, wtl_p, qb, kb, vb, nullptr, 0);

    attn_kernel<<<dim3(Nn / 128, Hh, Zb), 256, ATTN_SMEM>>>();

    // out-proj: A = ctx (hi/lo), B = Wo [1024][1024]
    gemm_fp16x3_kernel<<<dim3(Tt / 128, DM / 128), 256, GEMM_SMEM>>>(
        ctxh_p, ctxl_p, woh_p, wol_p, nullptr, nullptr, nullptr, out, 1);
}